// round 1
// baseline (speedup 1.0000x reference)
#include <cuda_runtime.h>
#include <cuda_bf16.h>
#include <stdint.h>

// Problem constants (TokenSelector: B=32, D=256, H=W=64)
#define BB 32
#define DD 256
#define NN 4096          // H*W
#define KK 2048          // NN * KEEP_RATIO

// ---------------- scratch (device globals; no allocation allowed) ----------
__device__ unsigned g_keys[BB * NN];   // monotone-sortable score keys
__device__ int      g_pos [BB * NN];   // output row position per token, -1 if dropped

// float -> monotone-increasing uint key
__device__ __forceinline__ unsigned f2k(float f) {
    unsigned u = __float_as_uint(f);
    return u ^ ((u >> 31) ? 0xFFFFFFFFu : 0x80000000u);
}

// ---------------------------------------------------------------------------
// Kernel 1: per-token score (logit ordering key).
// score = rstd * (dot(x, w') - mu * sum(w')),  w' = norm_w * fc_w
// (softmax, fc_b, norm_b are order-irrelevant: monotone / per-batch constants)
// grid: (NN/256, BB), block: 256. Thread handles one token n; loop over d
// strided by NN -> each iteration the block reads 1KB contiguous.
// ---------------------------------------------------------------------------
__global__ void score_kernel(const float* __restrict__ tokens,
                             const float* __restrict__ norm_w,
                             const float* __restrict__ fc_w,
                             unsigned*    __restrict__ keys)
{
    __shared__ float wsh[DD];
    int tid = threadIdx.x;
    wsh[tid] = norm_w[tid] * fc_w[tid];
    __syncthreads();

    int b = blockIdx.y;
    int n = blockIdx.x * 256 + tid;
    const float* p = tokens + (size_t)b * DD * NN + n;

    float s1 = 0.f, s2 = 0.f, sd = 0.f, sw = 0.f;
#pragma unroll 8
    for (int d = 0; d < DD; ++d) {
        float x = p[(size_t)d * NN];
        float w = wsh[d];
        s1 += x;
        s2 += x * x;
        sd += x * w;
        sw += w;
    }
    const float inv = 1.0f / (float)DD;
    float mu   = s1 * inv;
    float var  = fmaxf(s2 * inv - mu * mu, 0.f);
    float rstd = rsqrtf(var + 1e-5f);
    float score = (sd - mu * sw) * rstd;
    keys[b * NN + n] = f2k(score);
}

// ---------------------------------------------------------------------------
// Kernel 2: per-batch radix-select (K-th largest) + compaction.
// One block per batch, 1024 threads, keys in shared.
// Tie semantics match jax.lax.top_k: among equal-to-threshold values the
// lowest indices win; final index list is ascending (natural here).
// Writes g_pos[b][n] = output row (0..K-1) or -1.
// ---------------------------------------------------------------------------
__global__ void select_kernel(const unsigned* __restrict__ keys,
                              int* __restrict__ pos)
{
    __shared__ unsigned sk[NN];
    __shared__ int hist[256];
    __shared__ unsigned s_prefix;
    __shared__ int s_R;
    __shared__ int sgt[1024];
    __shared__ int seq[1024];

    int tid = threadIdx.x;
    int b   = blockIdx.x;
    const unsigned* kb = keys + b * NN;

#pragma unroll
    for (int i = tid; i < NN; i += 1024) sk[i] = kb[i];
    if (tid == 0) { s_prefix = 0u; s_R = KK; }
    __syncthreads();

    // MSB-first 8-bit radix select of the KK-th largest key
    unsigned mask = 0u;
    for (int shift = 24; shift >= 0; shift -= 8) {
        if (tid < 256) hist[tid] = 0;
        __syncthreads();
        unsigned prefix = s_prefix;
#pragma unroll
        for (int j = 0; j < 4; ++j) {
            unsigned key = sk[tid * 4 + j];
            if ((key & mask) == prefix)
                atomicAdd(&hist[(key >> shift) & 255u], 1);
        }
        __syncthreads();
        if (tid == 0) {
            int cum = 0, R = s_R;
            for (int bin = 255; bin >= 0; --bin) {
                int c = hist[bin];
                if (cum + c >= R) {
                    s_prefix = prefix | ((unsigned)bin << shift);
                    s_R = R - cum;   // how many ties (== threshold so far) still needed
                    break;
                }
                cum += c;
            }
        }
        mask |= (255u << shift);
        __syncthreads();
    }
    unsigned T = s_prefix;    // threshold key (the KK-th largest)
    int R = s_R;              // number of ==T keys to keep (lowest indices first)

    // Local counts over contiguous chunk n in [4*tid, 4*tid+4)
    int cg = 0, ce = 0;
    unsigned kloc[4];
#pragma unroll
    for (int j = 0; j < 4; ++j) {
        unsigned key = sk[tid * 4 + j];
        kloc[j] = key;
        cg += (key > T);
        ce += (key == T);
    }
    sgt[tid] = cg; seq[tid] = ce;
    __syncthreads();
    // Hillis–Steele inclusive scan over 1024 entries (two values fused)
    for (int off = 1; off < 1024; off <<= 1) {
        int a = 0, c = 0;
        if (tid >= off) { a = sgt[tid - off]; c = seq[tid - off]; }
        __syncthreads();
        if (tid >= off) { sgt[tid] += a; seq[tid] += c; }
        __syncthreads();
    }
    int g = sgt[tid] - cg;   // exclusive prefix: #(key>T) before my chunk
    int e = seq[tid] - ce;   // exclusive prefix: #(key==T) before my chunk

    int* pb = pos + b * NN;
#pragma unroll
    for (int j = 0; j < 4; ++j) {
        int n = tid * 4 + j;
        unsigned key = kloc[j];
        int kp = -1;
        if (key > T) {
            kp = g + min(e, R);
            ++g;
        } else if (key == T) {
            if (e < R) kp = g + e;
            ++e;
        }
        pb[n] = kp;
    }
}

// ---------------------------------------------------------------------------
// Kernel 3: streaming compaction-gather with shared-memory transpose.
// Block handles 32 source tokens x full D=256. Reads are fully coalesced
// (warp reads 32 consecutive n at fixed d); kept rows written as contiguous
// 1KB lines at out[b][pos][.].
// grid: (NN/32, BB), block: 256 (8 warps).
// ---------------------------------------------------------------------------
__global__ void gather_kernel(const float* __restrict__ tokens,
                              const int* __restrict__ pos,
                              float* __restrict__ out)
{
    __shared__ float tile[32][DD + 1];   // +1 pad: conflict-free transpose
    __shared__ int   spos[32];

    int tid  = threadIdx.x;
    int lane = tid & 31;
    int wid  = tid >> 5;        // 0..7
    int b    = blockIdx.y;
    int n0   = blockIdx.x * 32;

    if (tid < 32) spos[tid] = pos[b * NN + n0 + tid];

    const float* base = tokens + (size_t)b * DD * NN + n0 + lane;
#pragma unroll
    for (int j = 0; j < 32; ++j) {
        int d = wid + j * 8;
        tile[lane][d] = base[(size_t)d * NN];
    }
    __syncthreads();

    float* ob = out + (size_t)b * KK * DD;
#pragma unroll 4
    for (int kk = 0; kk < 32; ++kk) {
        int p = spos[kk];
        if (p >= 0) ob[(size_t)p * DD + tid] = tile[kk][tid];
    }
}

// ---------------------------------------------------------------------------
extern "C" void kernel_launch(void* const* d_in, const int* in_sizes, int n_in,
                              void* d_out, int out_size)
{
    const float* tokens = (const float*)d_in[0];
    const float* norm_w = (const float*)d_in[1];
    // d_in[2] = norm_b (order-irrelevant constant shift)
    const float* fc_w   = (const float*)d_in[3];
    // d_in[4] = fc_b   (order-irrelevant constant shift)
    float* out = (float*)d_out;

    unsigned* keys;
    int* pos;
    cudaGetSymbolAddress((void**)&keys, g_keys);
    cudaGetSymbolAddress((void**)&pos,  g_pos);

    score_kernel<<<dim3(NN / 256, BB), 256>>>(tokens, norm_w, fc_w, keys);
    select_kernel<<<BB, 1024>>>(keys, pos);
    gather_kernel<<<dim3(NN / 32, BB), 256>>>(tokens, pos, out);
}